// round 7
// baseline (speedup 1.0000x reference)
#include <cuda_runtime.h>
#include <cuda_bf16.h>

typedef unsigned long long ull;

#define H 256
#define S 200
#define BSZ 1024
#define BT 8
#define NITEMS 50000
#define KC 40            // k-pair slabs of W1/W2 cached in smem (of 128)
#define KCH (KC / 2)          // 20 cached kp per half
#define GKP ((128 - KC) / 2)  // 44 global kp per half

// ---------------- device globals (scratch; no allocs allowed) ----------------
__device__ ull   g_WhhP[128 * 768];          // packed (k,k+1) pairs, kp-major
__device__ ull   g_W1P[128 * 256];
__device__ ull   g_W2P[128 * 256];
__device__ float g_Etab[(size_t)NITEMS * 768];  // item_emb @ W_ih^T + b_ih
__device__ float g_hfin[BSZ * H];

// ---------------- f32x2 helpers ----------------
__device__ __forceinline__ void ffma2(ull& d, ull a, ull b) {
    asm("fma.rn.f32x2 %0, %1, %2, %3;" : "=l"(d) : "l"(a), "l"(b), "l"(d));
}
__device__ __forceinline__ ull pack2(float lo, float hi) {
    ull r; asm("mov.b64 %0, {%1, %2};" : "=l"(r) : "f"(lo), "f"(hi)); return r;
}
__device__ __forceinline__ void unpack2(ull v, float& lo, float& hi) {
    asm("mov.b64 {%0, %1}, %2;" : "=f"(lo), "=f"(hi) : "l"(v));
}
__device__ __forceinline__ float hsum2(ull v) {
    float lo, hi; unpack2(v, lo, hi); return lo + hi;
}
__device__ __forceinline__ float sigm(float v) { return 1.0f / (1.0f + __expf(-v)); }
__device__ __forceinline__ float ftanh(float v) {
    float e = __expf(2.0f * v);
    return 1.0f - 2.0f / (e + 1.0f);
}

// ---------------- weight packing ----------------
__global__ void prep_pack(const float* __restrict__ W_hh,
                          const float* __restrict__ W1,
                          const float* __restrict__ W2)
{
    int i = blockIdx.x * blockDim.x + threadIdx.x;
    if (i < 128 * 768) {
        int kp = i / 768, m = i % 768;
        g_WhhP[i] = pack2(W_hh[m * H + 2 * kp], W_hh[m * H + 2 * kp + 1]);
    }
    if (i < 128 * 256) {
        int kp = i / 256, jo = i % 256;
        g_W1P[i] = pack2(W1[jo * H + 2 * kp], W1[jo * H + 2 * kp + 1]);
        g_W2P[i] = pack2(W2[jo * H + 2 * kp], W2[jo * H + 2 * kp + 1]);
    }
}

// ---------------- generic C[M,N] = A[M,256] @ B[N,256]^T + bias ----------------
#define GM 64
#define GN 128

__global__ void __launch_bounds__(256) gemm_nt(
    const float* __restrict__ A, const float* __restrict__ B,
    const float* __restrict__ bias, float* __restrict__ C,
    int M, int N)
{
    __shared__ float shA[GM][H];     // 64 KB
    __shared__ float shW[8][132];    // staged W chunk (padded)

    const int n0 = blockIdx.x * GN;
    const int m0 = blockIdx.y * GM;
    const int tid = threadIdx.x;

#pragma unroll
    for (int i = 0; i < 16; i++) {
        int idx = tid + i * 256;              // 0..4095 float4s
        int r = idx >> 6, c4 = idx & 63;
        int m = m0 + r;
        float4 v = make_float4(0.f, 0.f, 0.f, 0.f);
        if (m < M) v = *(const float4*)&A[(size_t)m * H + c4 * 4];
        *(float4*)&shA[r][c4 * 4] = v;
    }

    const int tn = tid & 31;   // 32 n-groups of 4 cols
    const int tb = tid >> 5;   // 8 b-groups of 8 rows
    const int nl0 = tn * 4;

    ull acc[8][2];
#pragma unroll
    for (int bb = 0; bb < 8; bb++) { acc[bb][0] = 0ull; acc[bb][1] = 0ull; }

    __syncthreads();

    for (int k0 = 0; k0 < H; k0 += 8) {
#pragma unroll
        for (int i = 0; i < 4; i++) {
            int idx = tid + i * 256;          // 0..1023 -> 128 n x 8 k
            int nl = idx >> 3, kc = idx & 7;
            int n = n0 + nl;
            shW[kc][nl] = (n < N) ? B[(size_t)n * H + k0 + kc] : 0.f;
        }
        __syncthreads();
#pragma unroll
        for (int kc = 0; kc < 8; kc++) {
            ulonglong2 wv = *(const ulonglong2*)&shW[kc][nl0];
#pragma unroll
            for (int bb = 0; bb < 8; bb++) {
                float hb = shA[tb * 8 + bb][k0 + kc];
                ull hp = pack2(hb, hb);
                ffma2(acc[bb][0], hp, wv.x);
                ffma2(acc[bb][1], hp, wv.y);
            }
        }
        __syncthreads();
    }

    const int nbase = n0 + nl0;
#pragma unroll
    for (int bb = 0; bb < 8; bb++) {
        int m = m0 + tb * 8 + bb;
        if (m >= M) continue;
        float o0, o1, o2, o3;
        unpack2(acc[bb][0], o0, o1);
        unpack2(acc[bb][1], o2, o3);
        if (nbase + 3 < N) {
            float4 o;
            o.x = o0 + bias[nbase + 0];
            o.y = o1 + bias[nbase + 1];
            o.z = o2 + bias[nbase + 2];
            o.w = o3 + bias[nbase + 3];
            *(float4*)&C[(size_t)m * N + nbase] = o;
        } else {
            float ov[4] = {o0, o1, o2, o3};
#pragma unroll
            for (int nn = 0; nn < 4; nn++) {
                int n = nbase + nn;
                if (n < N) C[(size_t)m * N + n] = ov[nn] + bias[n];
            }
        }
    }
}

// ---------------- ODE partial matmul over this half's kp range ----------------
// Global weight loads issued FIRST (hidden behind smem-cached section), then
// global loop runs one pair ahead.
__device__ __forceinline__ void mm_partial(const float (*__restrict__ src)[H],
                                           const ull* __restrict__ ws,   // smem, abs kp<KC
                                           const ull* __restrict__ wg,   // global full
                                           int j, int half, ull* acc)
{
#pragma unroll
    for (int r = 0; r < BT; r++) acc[r] = 0ull;

    const int kg0 = KC + half * GKP;
    // issue first global pair now — covered by the cached section below
    ull ga0 = wg[(size_t)kg0 * H + j];
    ull ga1 = wg[(size_t)(kg0 + 1) * H + j];

    // cached: KCH kp per half = 10 pairs
    const int kc0 = half * KCH;
#pragma unroll 2
    for (int c = 0; c < KCH / 2; c++) {
        int kp = kc0 + 2 * c;
        ull w0 = ws[kp * H + j];
        ull w1 = ws[(kp + 1) * H + j];
#pragma unroll
        for (int r = 0; r < BT; r++) {
            ulonglong2 sv = *(const ulonglong2*)&src[r][2 * kp];
            ffma2(acc[r], sv.x, w0);
            ffma2(acc[r], sv.y, w1);
        }
    }

    // global: GKP kp per half = 22 pairs, 1-pair lookahead
#pragma unroll 1
    for (int c = 0; c < GKP / 2; c++) {
        ull gb0, gb1;
        if (c < GKP / 2 - 1) {
            gb0 = wg[(size_t)(kg0 + 2 * (c + 1)) * H + j];
            gb1 = wg[(size_t)(kg0 + 2 * (c + 1) + 1) * H + j];
        }
        int kp = kg0 + 2 * c;
#pragma unroll
        for (int r = 0; r < BT; r++) {
            ulonglong2 sv = *(const ulonglong2*)&src[r][2 * kp];
            ffma2(acc[r], sv.x, ga0);
            ffma2(acc[r], sv.y, ga1);
        }
        ga0 = gb0; ga1 = gb1;
    }
}

// ---------------- recurrent kernel: 512 threads, K split across 2 halves ----------------
__global__ void __launch_bounds__(512) rec_kernel(
    const int* __restrict__ x, const float* __restrict__ tt,
    const float* __restrict__ b_hh,
    const float* __restrict__ b1, const float* __restrict__ b2)
{
    extern __shared__ ull dynsmem[];
    ull* sW1 = dynsmem;                          // KC*256 ull
    ull* sW2 = dynsmem + KC * H;                 // KC*256 ull
    float* fbase = (float*)(dynsmem + 2 * KC * H);
    float (*sh_h)[H] = (float (*)[H])fbase;                  // 8x256
    float (*sh_a)[H] = (float (*)[H])(fbase + BT * H);       // 8x256
    float (*sh_t)[H] = (float (*)[H])(fbase + 2 * BT * H);   // 8x256
    float* red = fbase + 3 * BT * H;                         // 2 halves x 3 planes x 4 rows x 256

    const int tid = threadIdx.x;
    const int j = tid & 255;
    const int half = tid >> 8;
    const int r0 = half * 4;                     // this thread's 4 rows
    const int b0 = blockIdx.x * BT;

    // red slot: writer (j,h) stores rows of the OTHER half; reader (j,h) reads slot [1-h]
#define RG(hh, g, q) ((((hh) * 3 + (g)) * 4 + (q)) * H + j)

    // cache KC k-pair slabs of W1/W2 in smem
    for (int i = tid; i < KC * H; i += 512) { sW1[i] = g_W1P[i]; sW2[i] = g_W2P[i]; }

    const float bhhr = b_hh[j], bhhz = b_hh[H + j], bhhn = b_hh[2 * H + j];
    const float b1j = b1[j], b2j = b2[j];

#pragma unroll
    for (int q = 0; q < 4; q++) sh_h[r0 + q][j] = 0.f;
    float hnew[4];
#pragma unroll
    for (int q = 0; q < 4; q++) hnew[q] = 0.f;

    // per-thread (it, dt) for step 0, loaded up front (warp-uniform addresses)
    int   it4[4];
    float dt4[4];
#pragma unroll
    for (int q = 0; q < 4; q++) {
        int row = b0 + r0 + q;
        it4[q] = x[row * S];
        float tc = tt[row * S];
        float tn = tt[row * S + 1];
        dt4[q] = fmaxf(tn, tc + 1e-5f) - tc;   // S >= 2
    }
    __syncthreads();

    const ull* __restrict__ whh = g_WhhP;

    for (int s = 0; s < S; s++) {
        // ---- issue long-latency loads first: Etab gathers for current step ----
        float giR[4], giZ[4], giN[4];
#pragma unroll
        for (int q = 0; q < 4; q++) {
            const float* e = g_Etab + (size_t)it4[q] * 768;
            giR[q] = e[j];
            giZ[q] = e[H + j];
            giN[q] = e[2 * H + j];
        }

        // prefetch next step's (it, dt) into registers (static addresses)
        int   itn[4];
        float dtn[4];
        if (s + 1 < S) {
#pragma unroll
            for (int q = 0; q < 4; q++) {
                int row = b0 + r0 + q;
                itn[q] = x[row * S + s + 1];
                float tc = tt[row * S + s + 1];
                float d = 0.f;
                if (s + 1 < S - 1) {
                    float tn = tt[row * S + s + 2];
                    d = fmaxf(tn, tc + 1e-5f) - tc;
                }
                dtn[q] = d;
            }
        }

        // ---- GRU partial gate matmul over this half's 64 kp, 1-pair lookahead ----
        ull aR[BT], aZ[BT], aN[BT];
#pragma unroll
        for (int r = 0; r < BT; r++) { aR[r] = 0ull; aZ[r] = 0ull; aN[r] = 0ull; }

        const int kpb = half * 64;
        const ull* wp0 = whh + (size_t)kpb * 768 + j;
        ull wa0 = wp0[0],   wa1 = wp0[256],  wa2 = wp0[512];
        ull wa3 = wp0[768], wa4 = wp0[1024], wa5 = wp0[1280];

#pragma unroll 1
        for (int p = 0; p < 32; p++) {
            ull wb0, wb1, wb2, wb3, wb4, wb5;
            if (p < 31) {
                const ull* wn = whh + (size_t)(kpb + 2 * (p + 1)) * 768 + j;
                wb0 = wn[0];   wb1 = wn[256];  wb2 = wn[512];
                wb3 = wn[768]; wb4 = wn[1024]; wb5 = wn[1280];
            }
            const int kp = kpb + 2 * p;
#pragma unroll
            for (int r = 0; r < BT; r++) {
                ulonglong2 hv = *(const ulonglong2*)&sh_h[r][2 * kp];
                ffma2(aR[r], hv.x, wa0);
                ffma2(aZ[r], hv.x, wa1);
                ffma2(aN[r], hv.x, wa2);
                ffma2(aR[r], hv.y, wa3);
                ffma2(aZ[r], hv.y, wa4);
                ffma2(aN[r], hv.y, wa5);
            }
            wa0 = wb0; wa1 = wb1; wa2 = wb2; wa3 = wb3; wa4 = wb4; wa5 = wb5;
        }

        // write partials for the OTHER half's rows only (own stay in registers)
        {
            const int ro = (1 - half) * 4;
#pragma unroll
            for (int q = 0; q < 4; q++) {
                red[RG(half, 0, q)] = hsum2(aR[ro + q]);
                red[RG(half, 1, q)] = hsum2(aZ[ro + q]);
                red[RG(half, 2, q)] = hsum2(aN[ro + q]);
            }
        }
        __syncthreads();

        // combine + GRU elementwise for this thread's 4 rows
#pragma unroll
        for (int q = 0; q < 4; q++) {
            int r = r0 + q;
            float pR = hsum2(aR[r]) + red[RG(1 - half, 0, q)];
            float pZ = hsum2(aZ[r]) + red[RG(1 - half, 1, q)];
            float pN = hsum2(aN[r]) + red[RG(1 - half, 2, q)];
            float rg = sigm(giR[q] + pR + bhhr);
            float zg = sigm(giZ[q] + pZ + bhhz);
            float ng = ftanh(giN[q] + rg * (pN + bhhn));
            float hold = sh_h[r][j];
            hnew[q] = (1.f - zg) * ng + zg * hold;
            sh_h[r][j] = hnew[q];
        }
        __syncthreads();

        // ---- RK4 ----
        float ksum[4], kv[4];
        ull acc[BT];
        float (*src)[H] = sh_h;

#pragma unroll 1
        for (int eval = 0; eval < 4; eval++) {
            // layer 1
            mm_partial(src, sW1, g_W1P, j, half, acc);
            {
                const int ro = (1 - half) * 4;
#pragma unroll
                for (int q = 0; q < 4; q++) red[RG(half, 0, q)] = hsum2(acc[ro + q]);
            }
            __syncthreads();
#pragma unroll
            for (int q = 0; q < 4; q++) {
                int r = r0 + q;
                sh_a[r][j] = ftanh(hsum2(acc[r]) + red[RG(1 - half, 0, q)] + b1j);
            }
            __syncthreads();

            // layer 2
            mm_partial(sh_a, sW2, g_W2P, j, half, acc);
            {
                const int ro = (1 - half) * 4;
#pragma unroll
                for (int q = 0; q < 4; q++) red[RG(half, 0, q)] = hsum2(acc[ro + q]);
            }
            __syncthreads();
#pragma unroll
            for (int q = 0; q < 4; q++) {
                kv[q] = hsum2(acc[r0 + q]) + red[RG(1 - half, 0, q)] + b2j;
            }

            // RK4 bookkeeping + write next src (this thread's rows only)
            if (eval == 0) {
#pragma unroll
                for (int q = 0; q < 4; q++) {
                    ksum[q] = kv[q];
                    sh_t[r0 + q][j] = hnew[q] + 0.5f * dt4[q] * kv[q];
                }
            } else if (eval == 1) {
#pragma unroll
                for (int q = 0; q < 4; q++) {
                    ksum[q] += 2.f * kv[q];
                    sh_t[r0 + q][j] = hnew[q] + 0.5f * dt4[q] * kv[q];
                }
            } else if (eval == 2) {
#pragma unroll
                for (int q = 0; q < 4; q++) {
                    ksum[q] += 2.f * kv[q];
                    sh_t[r0 + q][j] = hnew[q] + dt4[q] * kv[q];
                }
            } else {
#pragma unroll
                for (int q = 0; q < 4; q++) {
                    ksum[q] += kv[q];
                    hnew[q] = hnew[q] + (dt4[q] * (1.f / 6.f)) * ksum[q];
                    sh_h[r0 + q][j] = hnew[q];
                }
            }
            __syncthreads();   // sh_t/sh_h visible; red reusable
            src = sh_t;
        }

        // roll prefetched inputs into place for next step
        if (s + 1 < S) {
#pragma unroll
            for (int q = 0; q < 4; q++) { it4[q] = itn[q]; dt4[q] = dtn[q]; }
        }
    }

#pragma unroll
    for (int q = 0; q < 4; q++) g_hfin[(b0 + r0 + q) * H + j] = hnew[q];
#undef RG
}

// ---------------- launch ----------------
extern "C" void kernel_launch(void* const* d_in, const int* in_sizes, int n_in,
                              void* d_out, int out_size)
{
    const int*   x      = (const int*)d_in[0];
    const float* t      = (const float*)d_in[1];
    const float* emb    = (const float*)d_in[2];
    const float* W_ih   = (const float*)d_in[3];
    const float* W_hh   = (const float*)d_in[4];
    const float* b_ih   = (const float*)d_in[5];
    const float* b_hh   = (const float*)d_in[6];
    const float* W1     = (const float*)d_in[7];
    const float* b1     = (const float*)d_in[8];
    const float* W2     = (const float*)d_in[9];
    const float* b2     = (const float*)d_in[10];
    const float* W_head = (const float*)d_in[11];
    const float* b_head = (const float*)d_in[12];
    float* out = (float*)d_out;

    float* etab_ptr = nullptr;
    float* hfin_ptr = nullptr;
    cudaGetSymbolAddress((void**)&etab_ptr, g_Etab);
    cudaGetSymbolAddress((void**)&hfin_ptr, g_hfin);

    const int smem_bytes = 2 * KC * H * (int)sizeof(ull)            // W1/W2 cache
                         + 3 * BT * H * (int)sizeof(float)          // h/a/t
                         + 2 * 3 * 4 * H * (int)sizeof(float);      // reduction buffer
    cudaFuncSetAttribute(rec_kernel, cudaFuncAttributeMaxDynamicSharedMemorySize, smem_bytes);

    prep_pack<<<(128 * 768 + 255) / 256, 256>>>(W_hh, W1, W2);

    // Etab = item_emb @ W_ih^T + b_ih   [50000, 768]
    dim3 ge(768 / GN, (NITEMS + GM - 1) / GM);
    gemm_nt<<<ge, 256>>>(emb, W_ih, b_ih, etab_ptr, NITEMS, 768);

    rec_kernel<<<BSZ / BT, 512, smem_bytes>>>(x, t, b_hh, b1, b2);

    // out = h_fin @ W_head^T + b_head   [1024, 50000]
    dim3 gh((NITEMS + GN - 1) / GN, BSZ / GM);
    gemm_nt<<<gh, 256>>>(hfin_ptr, W_head, b_head, out, BSZ, NITEMS);
}

// round 8
// speedup vs baseline: 1.5627x; 1.5627x over previous
#include <cuda_runtime.h>
#include <cuda_bf16.h>

typedef unsigned long long ull;

#define H 256
#define S 200
#define BSZ 1024
#define BT 8
#define NITEMS 50000
#define KC 40            // k-pair slabs of W1/W2 cached in smem (of 128)
#define KCH (KC / 2)          // 20 cached kp per half
#define GKP ((128 - KC) / 2)  // 44 global kp per half

// ---------------- device globals (scratch; no allocs allowed) ----------------
__device__ ull   g_WhhP[128 * 768];          // packed (k,k+1) pairs, kp-major
__device__ ull   g_W1P[128 * 256];
__device__ ull   g_W2P[128 * 256];
__device__ float g_Etab[(size_t)NITEMS * 768];  // item_emb @ W_ih^T + b_ih
__device__ float g_hfin[BSZ * H];

// ---------------- f32x2 helpers ----------------
__device__ __forceinline__ void ffma2(ull& d, ull a, ull b) {
    asm("fma.rn.f32x2 %0, %1, %2, %3;" : "=l"(d) : "l"(a), "l"(b), "l"(d));
}
__device__ __forceinline__ ull pack2(float lo, float hi) {
    ull r; asm("mov.b64 %0, {%1, %2};" : "=l"(r) : "f"(lo), "f"(hi)); return r;
}
__device__ __forceinline__ void unpack2(ull v, float& lo, float& hi) {
    asm("mov.b64 {%0, %1}, %2;" : "=f"(lo), "=f"(hi) : "l"(v));
}
__device__ __forceinline__ float hsum2(ull v) {
    float lo, hi; unpack2(v, lo, hi); return lo + hi;
}
__device__ __forceinline__ float sigm(float v) { return 1.0f / (1.0f + __expf(-v)); }
__device__ __forceinline__ float ftanh(float v) {
    float e = __expf(2.0f * v);
    return 1.0f - 2.0f / (e + 1.0f);
}

// ---------------- weight packing ----------------
__global__ void prep_pack(const float* __restrict__ W_hh,
                          const float* __restrict__ W1,
                          const float* __restrict__ W2)
{
    int i = blockIdx.x * blockDim.x + threadIdx.x;
    if (i < 128 * 768) {
        int kp = i / 768, m = i % 768;
        g_WhhP[i] = pack2(W_hh[m * H + 2 * kp], W_hh[m * H + 2 * kp + 1]);
    }
    if (i < 128 * 256) {
        int kp = i / 256, jo = i % 256;
        g_W1P[i] = pack2(W1[jo * H + 2 * kp], W1[jo * H + 2 * kp + 1]);
        g_W2P[i] = pack2(W2[jo * H + 2 * kp], W2[jo * H + 2 * kp + 1]);
    }
}

// ---------------- generic C[M,N] = A[M,256] @ B[N,256]^T + bias ----------------
#define GM 64
#define GN 128

__global__ void __launch_bounds__(256) gemm_nt(
    const float* __restrict__ A, const float* __restrict__ B,
    const float* __restrict__ bias, float* __restrict__ C,
    int M, int N)
{
    __shared__ float shA[GM][H];     // 64 KB
    __shared__ float shW[8][132];    // staged W chunk (padded)

    const int n0 = blockIdx.x * GN;
    const int m0 = blockIdx.y * GM;
    const int tid = threadIdx.x;

#pragma unroll
    for (int i = 0; i < 16; i++) {
        int idx = tid + i * 256;              // 0..4095 float4s
        int r = idx >> 6, c4 = idx & 63;
        int m = m0 + r;
        float4 v = make_float4(0.f, 0.f, 0.f, 0.f);
        if (m < M) v = *(const float4*)&A[(size_t)m * H + c4 * 4];
        *(float4*)&shA[r][c4 * 4] = v;
    }

    const int tn = tid & 31;   // 32 n-groups of 4 cols
    const int tb = tid >> 5;   // 8 b-groups of 8 rows
    const int nl0 = tn * 4;

    ull acc[8][2];
#pragma unroll
    for (int bb = 0; bb < 8; bb++) { acc[bb][0] = 0ull; acc[bb][1] = 0ull; }

    __syncthreads();

    for (int k0 = 0; k0 < H; k0 += 8) {
#pragma unroll
        for (int i = 0; i < 4; i++) {
            int idx = tid + i * 256;          // 0..1023 -> 128 n x 8 k
            int nl = idx >> 3, kc = idx & 7;
            int n = n0 + nl;
            shW[kc][nl] = (n < N) ? B[(size_t)n * H + k0 + kc] : 0.f;
        }
        __syncthreads();
#pragma unroll
        for (int kc = 0; kc < 8; kc++) {
            ulonglong2 wv = *(const ulonglong2*)&shW[kc][nl0];
#pragma unroll
            for (int bb = 0; bb < 8; bb++) {
                float hb = shA[tb * 8 + bb][k0 + kc];
                ull hp = pack2(hb, hb);
                ffma2(acc[bb][0], hp, wv.x);
                ffma2(acc[bb][1], hp, wv.y);
            }
        }
        __syncthreads();
    }

    const int nbase = n0 + nl0;
#pragma unroll
    for (int bb = 0; bb < 8; bb++) {
        int m = m0 + tb * 8 + bb;
        if (m >= M) continue;
        float o0, o1, o2, o3;
        unpack2(acc[bb][0], o0, o1);
        unpack2(acc[bb][1], o2, o3);
        if (nbase + 3 < N) {
            float4 o;
            o.x = o0 + bias[nbase + 0];
            o.y = o1 + bias[nbase + 1];
            o.z = o2 + bias[nbase + 2];
            o.w = o3 + bias[nbase + 3];
            *(float4*)&C[(size_t)m * N + nbase] = o;
        } else {
            float ov[4] = {o0, o1, o2, o3};
#pragma unroll
            for (int nn = 0; nn < 4; nn++) {
                int n = nbase + nn;
                if (n < N) C[(size_t)m * N + n] = ov[nn] + bias[n];
            }
        }
    }
}

// ---------------- ODE partial matmul over this half's kp range ----------------
// Global weight loads issued FIRST (hidden behind smem-cached section), then
// global loop runs one pair ahead.
__device__ __forceinline__ void mm_partial(const float (*__restrict__ src)[H],
                                           const ull* __restrict__ ws,   // smem, abs kp<KC
                                           const ull* __restrict__ wg,   // global full
                                           int j, int half, ull* acc)
{
#pragma unroll
    for (int r = 0; r < BT; r++) acc[r] = 0ull;

    const int kg0 = KC + half * GKP;
    // issue first global pair now — covered by the cached section below
    ull ga0 = wg[(size_t)kg0 * H + j];
    ull ga1 = wg[(size_t)(kg0 + 1) * H + j];

    // cached: KCH kp per half = 10 pairs
    const int kc0 = half * KCH;
#pragma unroll 2
    for (int c = 0; c < KCH / 2; c++) {
        int kp = kc0 + 2 * c;
        ull w0 = ws[kp * H + j];
        ull w1 = ws[(kp + 1) * H + j];
#pragma unroll
        for (int r = 0; r < BT; r++) {
            ulonglong2 sv = *(const ulonglong2*)&src[r][2 * kp];
            ffma2(acc[r], sv.x, w0);
            ffma2(acc[r], sv.y, w1);
        }
    }

    // global: GKP kp per half = 22 pairs, 1-pair lookahead
#pragma unroll 1
    for (int c = 0; c < GKP / 2; c++) {
        ull gb0, gb1;
        if (c < GKP / 2 - 1) {
            gb0 = wg[(size_t)(kg0 + 2 * (c + 1)) * H + j];
            gb1 = wg[(size_t)(kg0 + 2 * (c + 1) + 1) * H + j];
        }
        int kp = kg0 + 2 * c;
#pragma unroll
        for (int r = 0; r < BT; r++) {
            ulonglong2 sv = *(const ulonglong2*)&src[r][2 * kp];
            ffma2(acc[r], sv.x, ga0);
            ffma2(acc[r], sv.y, ga1);
        }
        ga0 = gb0; ga1 = gb1;
    }
}

// ---------------- recurrent kernel: 512 threads, K split across 2 halves ----------------
__global__ void __launch_bounds__(512) rec_kernel(
    const int* __restrict__ x, const float* __restrict__ tt,
    const float* __restrict__ b_hh,
    const float* __restrict__ b1, const float* __restrict__ b2)
{
    extern __shared__ ull dynsmem[];
    ull* sW1 = dynsmem;                          // KC*256 ull
    ull* sW2 = dynsmem + KC * H;                 // KC*256 ull
    float* fbase = (float*)(dynsmem + 2 * KC * H);
    float (*sh_h)[H] = (float (*)[H])fbase;                  // 8x256
    float (*sh_a)[H] = (float (*)[H])(fbase + BT * H);       // 8x256
    float (*sh_t)[H] = (float (*)[H])(fbase + 2 * BT * H);   // 8x256
    float* red = fbase + 3 * BT * H;                         // 2 halves x 3 planes x 4 rows x 256

    const int tid = threadIdx.x;
    const int j = tid & 255;
    const int half = tid >> 8;
    const int r0 = half * 4;                     // this thread's 4 rows
    const int b0 = blockIdx.x * BT;

    // red slot: writer (j,h) stores rows of the OTHER half; reader (j,h) reads slot [1-h]
#define RG(hh, g, q) ((((hh) * 3 + (g)) * 4 + (q)) * H + j)

    // cache KC k-pair slabs of W1/W2 in smem
    for (int i = tid; i < KC * H; i += 512) { sW1[i] = g_W1P[i]; sW2[i] = g_W2P[i]; }

    const float bhhr = b_hh[j], bhhz = b_hh[H + j], bhhn = b_hh[2 * H + j];
    const float b1j = b1[j], b2j = b2[j];

#pragma unroll
    for (int q = 0; q < 4; q++) sh_h[r0 + q][j] = 0.f;
    float hnew[4];
#pragma unroll
    for (int q = 0; q < 4; q++) hnew[q] = 0.f;

    // per-thread (it, dt) for step 0, loaded up front (warp-uniform addresses)
    int   it4[4];
    float dt4[4];
#pragma unroll
    for (int q = 0; q < 4; q++) {
        int row = b0 + r0 + q;
        it4[q] = x[row * S];
        float tc = tt[row * S];
        float tn = tt[row * S + 1];
        dt4[q] = fmaxf(tn, tc + 1e-5f) - tc;   // S >= 2
    }
    __syncthreads();

    const ull* __restrict__ whh = g_WhhP;

    for (int s = 0; s < S; s++) {
        // ---- issue long-latency loads first: Etab gathers for current step ----
        float giR[4], giZ[4], giN[4];
#pragma unroll
        for (int q = 0; q < 4; q++) {
            const float* e = g_Etab + (size_t)it4[q] * 768;
            giR[q] = e[j];
            giZ[q] = e[H + j];
            giN[q] = e[2 * H + j];
        }

        // prefetch next step's (it, dt) into registers (static addresses)
        int   itn[4];
        float dtn[4];
        if (s + 1 < S) {
#pragma unroll
            for (int q = 0; q < 4; q++) {
                int row = b0 + r0 + q;
                itn[q] = x[row * S + s + 1];
                float tc = tt[row * S + s + 1];
                float d = 0.f;
                if (s + 1 < S - 1) {
                    float tn = tt[row * S + s + 2];
                    d = fmaxf(tn, tc + 1e-5f) - tc;
                }
                dtn[q] = d;
            }
        }

        // ---- GRU partial gate matmul over this half's 64 kp, 1-pair lookahead ----
        ull aR[BT], aZ[BT], aN[BT];
#pragma unroll
        for (int r = 0; r < BT; r++) { aR[r] = 0ull; aZ[r] = 0ull; aN[r] = 0ull; }

        const int kpb = half * 64;
        const ull* wp0 = whh + (size_t)kpb * 768 + j;
        ull wa0 = wp0[0],   wa1 = wp0[256],  wa2 = wp0[512];
        ull wa3 = wp0[768], wa4 = wp0[1024], wa5 = wp0[1280];

#pragma unroll 1
        for (int p = 0; p < 32; p++) {
            ull wb0, wb1, wb2, wb3, wb4, wb5;
            if (p < 31) {
                const ull* wn = whh + (size_t)(kpb + 2 * (p + 1)) * 768 + j;
                wb0 = wn[0];   wb1 = wn[256];  wb2 = wn[512];
                wb3 = wn[768]; wb4 = wn[1024]; wb5 = wn[1280];
            }
            const int kp = kpb + 2 * p;
#pragma unroll
            for (int r = 0; r < BT; r++) {
                ulonglong2 hv = *(const ulonglong2*)&sh_h[r][2 * kp];
                ffma2(aR[r], hv.x, wa0);
                ffma2(aZ[r], hv.x, wa1);
                ffma2(aN[r], hv.x, wa2);
                ffma2(aR[r], hv.y, wa3);
                ffma2(aZ[r], hv.y, wa4);
                ffma2(aN[r], hv.y, wa5);
            }
            wa0 = wb0; wa1 = wb1; wa2 = wb2; wa3 = wb3; wa4 = wb4; wa5 = wb5;
        }

        // write partials for the OTHER half's rows only (own stay in registers)
        {
            const int ro = (1 - half) * 4;
#pragma unroll
            for (int q = 0; q < 4; q++) {
                red[RG(half, 0, q)] = hsum2(aR[ro + q]);
                red[RG(half, 1, q)] = hsum2(aZ[ro + q]);
                red[RG(half, 2, q)] = hsum2(aN[ro + q]);
            }
        }
        __syncthreads();

        // combine + GRU elementwise for this thread's 4 rows
#pragma unroll
        for (int q = 0; q < 4; q++) {
            int r = r0 + q;
            float pR = hsum2(aR[r]) + red[RG(1 - half, 0, q)];
            float pZ = hsum2(aZ[r]) + red[RG(1 - half, 1, q)];
            float pN = hsum2(aN[r]) + red[RG(1 - half, 2, q)];
            float rg = sigm(giR[q] + pR + bhhr);
            float zg = sigm(giZ[q] + pZ + bhhz);
            float ng = ftanh(giN[q] + rg * (pN + bhhn));
            float hold = sh_h[r][j];
            hnew[q] = (1.f - zg) * ng + zg * hold;
            sh_h[r][j] = hnew[q];
        }
        __syncthreads();

        // ---- RK4 ----
        float ksum[4], kv[4];
        ull acc[BT];
        float (*src)[H] = sh_h;

#pragma unroll 1
        for (int eval = 0; eval < 4; eval++) {
            // layer 1
            mm_partial(src, sW1, g_W1P, j, half, acc);
            {
                const int ro = (1 - half) * 4;
#pragma unroll
                for (int q = 0; q < 4; q++) red[RG(half, 0, q)] = hsum2(acc[ro + q]);
            }
            __syncthreads();
#pragma unroll
            for (int q = 0; q < 4; q++) {
                int r = r0 + q;
                sh_a[r][j] = ftanh(hsum2(acc[r]) + red[RG(1 - half, 0, q)] + b1j);
            }
            __syncthreads();

            // layer 2
            mm_partial(sh_a, sW2, g_W2P, j, half, acc);
            {
                const int ro = (1 - half) * 4;
#pragma unroll
                for (int q = 0; q < 4; q++) red[RG(half, 0, q)] = hsum2(acc[ro + q]);
            }
            __syncthreads();
#pragma unroll
            for (int q = 0; q < 4; q++) {
                kv[q] = hsum2(acc[r0 + q]) + red[RG(1 - half, 0, q)] + b2j;
            }

            // RK4 bookkeeping + write next src (this thread's rows only)
            if (eval == 0) {
#pragma unroll
                for (int q = 0; q < 4; q++) {
                    ksum[q] = kv[q];
                    sh_t[r0 + q][j] = hnew[q] + 0.5f * dt4[q] * kv[q];
                }
            } else if (eval == 1) {
#pragma unroll
                for (int q = 0; q < 4; q++) {
                    ksum[q] += 2.f * kv[q];
                    sh_t[r0 + q][j] = hnew[q] + 0.5f * dt4[q] * kv[q];
                }
            } else if (eval == 2) {
#pragma unroll
                for (int q = 0; q < 4; q++) {
                    ksum[q] += 2.f * kv[q];
                    sh_t[r0 + q][j] = hnew[q] + dt4[q] * kv[q];
                }
            } else {
#pragma unroll
                for (int q = 0; q < 4; q++) {
                    ksum[q] += kv[q];
                    hnew[q] = hnew[q] + (dt4[q] * (1.f / 6.f)) * ksum[q];
                    sh_h[r0 + q][j] = hnew[q];
                }
            }
            __syncthreads();   // sh_t/sh_h visible; red reusable
            src = sh_t;
        }

        // roll prefetched inputs into place for next step
        if (s + 1 < S) {
#pragma unroll
            for (int q = 0; q < 4; q++) { it4[q] = itn[q]; dt4[q] = dtn[q]; }
        }
    }

#pragma unroll
    for (int q = 0; q < 4; q++) g_hfin[(b0 + r0 + q) * H + j] = hnew[q];
#undef RG
}

// ---------------- launch ----------------
extern "C" void kernel_launch(void* const* d_in, const int* in_sizes, int n_in,
                              void* d_out, int out_size)
{
    const int*   x      = (const int*)d_in[0];
    const float* t      = (const float*)d_in[1];
    const float* emb    = (const float*)d_in[2];
    const float* W_ih   = (const float*)d_in[3];
    const float* W_hh   = (const float*)d_in[4];
    const float* b_ih   = (const float*)d_in[5];
    const float* b_hh   = (const float*)d_in[6];
    const float* W1     = (const float*)d_in[7];
    const float* b1     = (const float*)d_in[8];
    const float* W2     = (const float*)d_in[9];
    const float* b2     = (const float*)d_in[10];
    const float* W_head = (const float*)d_in[11];
    const float* b_head = (const float*)d_in[12];
    float* out = (float*)d_out;

    float* etab_ptr = nullptr;
    float* hfin_ptr = nullptr;
    cudaGetSymbolAddress((void**)&etab_ptr, g_Etab);
    cudaGetSymbolAddress((void**)&hfin_ptr, g_hfin);

    const int smem_bytes = 2 * KC * H * (int)sizeof(ull)            // W1/W2 cache
                         + 3 * BT * H * (int)sizeof(float)          // h/a/t
                         + 2 * 3 * 4 * H * (int)sizeof(float);      // reduction buffer
    cudaFuncSetAttribute(rec_kernel, cudaFuncAttributeMaxDynamicSharedMemorySize, smem_bytes);

    prep_pack<<<(128 * 768 + 255) / 256, 256>>>(W_hh, W1, W2);

    // Etab = item_emb @ W_ih^T + b_ih   [50000, 768]
    dim3 ge(768 / GN, (NITEMS + GM - 1) / GM);
    gemm_nt<<<ge, 256>>>(emb, W_ih, b_ih, etab_ptr, NITEMS, 768);

    rec_kernel<<<BSZ / BT, 512, smem_bytes>>>(x, t, b_hh, b1, b2);

    // out = h_fin @ W_head^T + b_head   [1024, 50000]
    dim3 gh((NITEMS + GN - 1) / GN, BSZ / GM);
    gemm_nt<<<gh, 256>>>(hfin_ptr, W_head, b_head, out, BSZ, NITEMS);
}